// round 12
// baseline (speedup 1.0000x reference)
#include <cuda_runtime.h>
#include <cuda_bf16.h>
#include <math.h>

// ---------------- problem constants ----------------
#define MAXN 50000
#define MAXE 800000
#define D12  256

// ---------------- scratch (device globals, compile-time symbol refs only) ---
__device__ float g_bufA[MAXN * D12];       // h (post-GEMM)
__device__ float g_bufB[MAXN * D12];       // aggregated output
__device__ unsigned g_Wf[122880];          // precomputed bf16 B-fragment table
__device__ float g_als[MAXN * 4];
__device__ float g_ald[MAXN * 4];
__device__ float g_pcomb[MAXN * 128];      // [prow | pcol] combined
__device__ int g_deg[MAXN];
__device__ int g_off[MAXN + 1];
__device__ int g_cur[MAXN];
__device__ int g_csr[MAXE];

// fragment-table offsets (words)
#define FW1   0        // 32*256   = 8192   (nBn=4, K=32)
#define FW2   8192     // 256*256  = 65536  (nBn=4, K=256)
#define FW3   73728    // 256*128  = 32768  (nBn=2, K=256)
#define FPC   106496   // 128*128  = 16384  (nBn=2, K=128, block-structured mw1)

__device__ __forceinline__ unsigned pack_bf16(float lo, float hi) {
    unsigned d;
    asm("cvt.rn.bf16x2.f32 %0, %1, %2;" : "=r"(d) : "f"(hi), "f"(lo));
    return d;
}

// ---------------- one-time weight split into mma fragment layout -----------
__global__ void wsplit_kernel(const float* W1, const float* W2, const float* W3,
                              const float* mw1) {
    int w = blockIdx.x * blockDim.x + threadIdx.x;
    if (w >= 122880) return;
    const float* src;
    int srcNc, nBn, rel, pcMode;
    if (w < 8192)        { src = W1;  srcNc = 256; nBn = 4; rel = w;          pcMode = 0; }
    else if (w < 73728)  { src = W2;  srcNc = 256; nBn = 4; rel = w - 8192;   pcMode = 0; }
    else if (w < 106496) { src = W3;  srcNc = 128; nBn = 2; rel = w - 73728;  pcMode = 0; }
    else                 { src = mw1; srcNc = 64;  nBn = 2; rel = w - 106496; pcMode = 1; }
    int tile = rel >> 10;
    int r = rel & 1023;
    int ni = r >> 7;
    int lane = (r >> 2) & 31;
    int sub = r & 3;
    int bs = sub >> 1, bw = sub & 1;
    int g = lane >> 2, tg = lane & 3;
    int bn = tile % nBn, t = tile / nBn;
    int P = tg + bw * 4;
    int colWithin = ni * 8 + g;
    int col = pcMode ? colWithin : (bn * 64 + colWithin);
    int k = (pcMode ? bn * 128 : 0) + t * 16 + 2 * P;
    float x0 = src[k * srcNc + col];
    float x1 = src[(k + 1) * srcNc + col];
    unsigned big = pack_bf16(x0, x1);
    float lo = __uint_as_float(big << 16);
    float hi = __uint_as_float(big & 0xffff0000u);
    unsigned sml = pack_bf16(x0 - lo, x1 - hi);
    g_Wf[w] = bs ? sml : big;
}

// ---------------- CSR construction ----------------
__global__ void zero_deg_kernel(int n) {
    int i = blockIdx.x * blockDim.x + threadIdx.x;
    if (i < n) g_deg[i] = 0;
}

__global__ void hist_kernel(const int* ei, int E) {
    int i = blockIdx.x * blockDim.x + threadIdx.x;
    if (i < E) atomicAdd(&g_deg[ei[E + i]], 1);
}

// warp-shuffle block scan: 1024 threads, each owns a contiguous run.
__global__ void scan_kernel(int n) {
    __shared__ int warpsum[32];
    int tid = threadIdx.x;
    int per = (n + 1023) >> 10;
    int start = tid * per;
    int end = min(start + per, n);
    int s = 0;
    for (int i = start; i < end; i++) s += g_deg[i];

    int lane = tid & 31, wid = tid >> 5;
    int incl = s;
#pragma unroll
    for (int o = 1; o < 32; o <<= 1) {
        int v = __shfl_up_sync(0xffffffffu, incl, o);
        if (lane >= o) incl += v;
    }
    if (lane == 31) warpsum[wid] = incl;
    __syncthreads();
    if (wid == 0) {
        int w = warpsum[lane];
        int wi = w;
#pragma unroll
        for (int o = 1; o < 32; o <<= 1) {
            int v = __shfl_up_sync(0xffffffffu, wi, o);
            if (lane >= o) wi += v;
        }
        warpsum[lane] = wi - w;   // exclusive warp prefix
    }
    __syncthreads();
    int run = (incl - s) + warpsum[wid];   // exclusive prefix for this thread
    for (int i = start; i < end; i++) {
        int d = g_deg[i];
        g_off[i] = run;
        g_cur[i] = run;
        run += d;
    }
    if (tid == 1023) g_off[n] = run;
}

__global__ void scatter_kernel(const int* ei, int E) {
    int i = blockIdx.x * blockDim.x + threadIdx.x;
    if (i < E) {
        int d = ei[E + i];
        int s = ei[i];
        int p = atomicAdd(&g_cur[d], 1);
        g_csr[p] = s;
    }
}

// ---------------- 3-term bf16 tensor-core GEMM (double-buffered A) ---------
__device__ __forceinline__ void mma_bf16(float& d0, float& d1, float& d2, float& d3,
                                         unsigned a0, unsigned a1, unsigned a2, unsigned a3,
                                         unsigned b0, unsigned b1) {
    asm volatile(
        "mma.sync.aligned.m16n8k16.row.col.f32.bf16.bf16.f32 "
        "{%0,%1,%2,%3}, {%4,%5,%6,%7}, {%8,%9}, {%0,%1,%2,%3};"
        : "+f"(d0), "+f"(d1), "+f"(d2), "+f"(d3)
        : "r"(a0), "r"(a1), "r"(a2), "r"(a3), "r"(b0), "r"(b1));
}

template <int ASRC, int CSEL>
__global__ void __launch_bounds__(256) gemm_bf_kernel(const float* Aext, int fbase,
                                                      int nBn, int M, int K) {
    const float* A;
    if constexpr (ASRC == 0) A = Aext; else A = (const float*)g_bufB;
    float* C;
    if constexpr (CSEL == 0) C = g_bufA; else C = g_pcomb;
    int Nc = nBn * 64;

    __shared__ unsigned sAb[2][1024];
    __shared__ unsigned sAs[2][1024];

    int tid = threadIdx.x;
    int bm = blockIdx.y * 128;
    int bn = blockIdx.x;
    int warpId = tid >> 5;
    int lane = tid & 31;
    int g = lane >> 2;
    int tg = lane & 3;
    int wCol = (warpId >> 2) * 32;
    int wTile0 = (warpId & 3) * 2;

    int ar = tid >> 1;
    int khalf = tid & 1;
    int att = ar >> 4;
    int asub = ar & 15;
    int ahi = asub >> 3;
    int agg = asub & 7;

    float d[2][4][4];
#pragma unroll
    for (int mi = 0; mi < 2; mi++)
#pragma unroll
        for (int ni = 0; ni < 4; ni++)
#pragma unroll
            for (int q = 0; q < 4; q++) d[mi][ni][q] = 0.f;

    const unsigned* Wf = (const unsigned*)g_Wf;
    int p = 0;

    for (int k0 = 0; k0 < K; k0 += 16, p ^= 1) {
        int t = k0 >> 4;
        uint4 bfr[4];
        {
            const uint4* fb = (const uint4*)(Wf + fbase + (size_t)(t * nBn + bn) * 1024);
#pragma unroll
            for (int nj = 0; nj < 4; nj++)
                bfr[nj] = fb[((wCol >> 3) + nj) * 32 + lane];
        }
        {
            float4 v0 = make_float4(0.f, 0.f, 0.f, 0.f);
            float4 v1 = make_float4(0.f, 0.f, 0.f, 0.f);
            if (bm + ar < M) {
                const float* pp = A + (size_t)(bm + ar) * K + k0 + khalf * 8;
                v0 = *(const float4*)pp;
                v1 = *(const float4*)(pp + 4);
            }
            float xs[8] = {v0.x, v0.y, v0.z, v0.w, v1.x, v1.y, v1.z, v1.w};
#pragma unroll
            for (int p2 = 0; p2 < 4; p2++) {
                int wsl = khalf * 2 + ahi;
                int slot = p2 ^ ((agg >> 1) & 3);
                int idx = att * 128 + (agg * 4 + slot) * 4 + wsl;
                unsigned big = pack_bf16(xs[2 * p2], xs[2 * p2 + 1]);
                float lo = __uint_as_float(big << 16);
                float hi = __uint_as_float(big & 0xffff0000u);
                sAb[p][idx] = big;
                sAs[p][idx] = pack_bf16(xs[2 * p2] - lo, xs[2 * p2 + 1] - hi);
            }
        }
        __syncthreads();

        uint4 afb[2], afs[2];
#pragma unroll
        for (int mi = 0; mi < 2; mi++) {
            int base = (wTile0 + mi) * 128 + (g * 4 + (tg ^ ((g >> 1) & 3))) * 4;
            afb[mi] = *(const uint4*)&sAb[p][base];
            afs[mi] = *(const uint4*)&sAs[p][base];
        }

#pragma unroll
        for (int ni = 0; ni < 4; ni++) {
            uint4 b = bfr[ni];
#pragma unroll
            for (int mi = 0; mi < 2; mi++) {
                float* dd = d[mi][ni];
                mma_bf16(dd[0], dd[1], dd[2], dd[3],
                         afb[mi].x, afb[mi].y, afb[mi].z, afb[mi].w, b.x, b.y);
                mma_bf16(dd[0], dd[1], dd[2], dd[3],
                         afb[mi].x, afb[mi].y, afb[mi].z, afb[mi].w, b.z, b.w);
                mma_bf16(dd[0], dd[1], dd[2], dd[3],
                         afs[mi].x, afs[mi].y, afs[mi].z, afs[mi].w, b.x, b.y);
            }
        }
    }

#pragma unroll
    for (int mi = 0; mi < 2; mi++) {
#pragma unroll
        for (int ni = 0; ni < 4; ni++) {
            int row0 = bm + (wTile0 + mi) * 16 + g;
            int col = bn * 64 + wCol + ni * 8 + tg * 2;
            if (row0 < M)
                *(float2*)(C + (size_t)row0 * Nc + col) = make_float2(d[mi][ni][0], d[mi][ni][1]);
            if (row0 + 8 < M)
                *(float2*)(C + (size_t)(row0 + 8) * Nc + col) = make_float2(d[mi][ni][2], d[mi][ni][3]);
        }
    }
}

// ---------------- per-node attention coefficients ----------------
__global__ void al_kernel(const float* as, const float* ad, int N, int H, int C) {
    int gw = (blockIdx.x * blockDim.x + threadIdx.x) >> 5;
    int lane = threadIdx.x & 31;
    int n = gw / H;
    int hd = gw % H;
    if (n >= N) return;
    size_t base = (size_t)n * H * C + (size_t)hd * C;
    float s1 = 0.f, s2 = 0.f;
    for (int c = lane; c < C; c += 32) {
        float v = g_bufA[base + c];
        s1 = fmaf(v, as[hd * C + c], s1);
        s2 = fmaf(v, ad[hd * C + c], s2);
    }
#pragma unroll
    for (int o = 16; o; o >>= 1) {
        s1 += __shfl_down_sync(0xffffffffu, s1, o);
        s2 += __shfl_down_sync(0xffffffffu, s2, o);
    }
    if (lane == 0) {
        g_als[n * H + hd] = s1;
        g_ald[n * H + hd] = s2;
    }
}

// ---------------- GAT aggregation, SINGLE PASS (no max subtraction) --------
// Valid because |logits| << 88 here (0.1-scaled weights, O(1) activations).
// acc accumulates unnormalized exp-weighted h; z reduced via shared atomics;
// normalization folded into the epilogue. bufA -> bufB.
template <int H, int C>
__global__ void agg_kernel(const float* bias, int applyElu) {
    const int D2 = H * C / 2;               // threads
    const int CHUNK = (H == 4) ? 32 : 64;   // = blockDim / H
    int n = blockIdx.x;
    int t = threadIdx.x;
    __shared__ float sh_alpha[CHUNK * H];
    __shared__ int sh_src[CHUNK];
    __shared__ float sh_z[H];

    int o0 = g_off[n];
    int deg = g_off[n + 1] - o0;
    int head = t / (C / 2);

    if (t < H) sh_z[t] = 0.f;

    // staging role (fixed per thread): j = t/H, hd = t%H
    int sj = t / H;
    int shd = t % H;
    float adn = g_ald[n * H + shd];
    float zloc = 0.f;

    float2 acc = make_float2(0.f, 0.f);
    int total = deg + 1;
    const float2* h2 = (const float2*)g_bufA;
    for (int base = 0; base < total; base += CHUNK) {
        int cnt = min(CHUNK, total - base);
        if (sj < cnt) {
            int src = (base + sj < deg) ? g_csr[o0 + base + sj] : n;
            if (shd == 0) sh_src[sj] = src;
            float att = g_als[src * H + shd] + adn;
            att = att > 0.f ? att : 0.2f * att;
            float w = __expf(att);
            sh_alpha[sj * H + shd] = w;
            zloc += w;
        }
        __syncthreads();
#pragma unroll 4
        for (int j = 0; j < cnt; j++) {
            float2 v = h2[(size_t)sh_src[j] * D2 + t];
            float a = sh_alpha[j * H + head];
            acc.x = fmaf(v.x, a, acc.x);
            acc.y = fmaf(v.y, a, acc.y);
        }
        __syncthreads();
    }
    atomicAdd(&sh_z[shd], zloc);
    __syncthreads();

    float iz = 1.0f / sh_z[head];
    float rx = fmaf(acc.x, iz, bias[2 * t]);
    float ry = fmaf(acc.y, iz, bias[2 * t + 1]);
    if (applyElu) {
        rx = rx > 0.f ? rx : expm1f(rx);
        ry = ry > 0.f ? ry : expm1f(ry);
    }
    *(float2*)(g_bufB + (size_t)n * (2 * D2) + 2 * t) = make_float2(rx, ry);
}

// ---------------- edge MLP: 2 edges per warp, float2-packed sw2 ------------
__global__ void __launch_bounds__(1024) edge_mlp_kernel(const int* ei, const float* ea,
                                const float* mw1, const float* mb1,
                                const float* mw2, const float* mb2,
                                const float* mw3, const float* mb3,
                                float* out, int E) {
    __shared__ float2 sw2t[1024];
    int tid = threadIdx.x;
    {
        int sl = tid >> 5, ln = tid & 31;
        sw2t[tid] = make_float2(mw2[sl * 64 + ln], mw2[sl * 64 + 32 + ln]);
    }
    __syncthreads();

    int warp = (int)((blockIdx.x * (size_t)blockDim.x + tid) >> 5);
    int lane = tid & 31;
    int e0 = warp * 2;
    if (e0 >= E) return;
    bool has2 = (e0 + 1 < E);
    int e1 = has2 ? e0 + 1 : e0;

    int rowA = ei[e0], colA = ei[E + e0];
    int rowB = ei[e1], colB = ei[E + e1];
    float eaA0 = ea[e0 * 2], eaA1 = ea[e0 * 2 + 1];
    float eaB0 = ea[e1 * 2], eaB1 = ea[e1 * 2 + 1];

    int j0 = lane * 2;
    float w1e0 = mw1[256 * 64 + j0], w1e0b = mw1[256 * 64 + j0 + 1];
    float w1e1 = mw1[257 * 64 + j0], w1e1b = mw1[257 * 64 + j0 + 1];
    float bj0 = mb1[j0], bj1 = mb1[j0 + 1];

    float2 prA = *(const float2*)(g_pcomb + (size_t)rowA * 128 + j0);
    float2 pcA = *(const float2*)(g_pcomb + (size_t)colA * 128 + 64 + j0);
    float2 prB = *(const float2*)(g_pcomb + (size_t)rowB * 128 + j0);
    float2 pcB = *(const float2*)(g_pcomb + (size_t)colB * 128 + 64 + j0);

    float o1aA = fmaxf(prA.x + pcA.x + eaA0 * w1e0 + eaA1 * w1e1 + bj0, 0.f);
    float o1bA = fmaxf(prA.y + pcA.y + eaA0 * w1e0b + eaA1 * w1e1b + bj1, 0.f);
    float o1aB = fmaxf(prB.x + pcB.x + eaB0 * w1e0 + eaB1 * w1e1 + bj0, 0.f);
    float o1bB = fmaxf(prB.y + pcB.y + eaB0 * w1e0b + eaB1 * w1e1b + bj1, 0.f);

    float accA = mb2[lane];
    float accB = accA;
#pragma unroll
    for (int sl = 0; sl < 32; sl++) {
        float2 w = sw2t[sl * 32 + lane];
        float vaA = __shfl_sync(0xffffffffu, o1aA, sl);
        float vbA = __shfl_sync(0xffffffffu, o1bA, sl);
        float vaB = __shfl_sync(0xffffffffu, o1aB, sl);
        float vbB = __shfl_sync(0xffffffffu, o1bB, sl);
        accA = fmaf(vaA, w.x, accA);
        accA = fmaf(vbA, w.y, accA);
        accB = fmaf(vaB, w.x, accB);
        accB = fmaf(vbB, w.y, accB);
    }
    accA = fmaxf(accA, 0.f);
    accB = fmaxf(accB, 0.f);

    float w3 = mw3[lane];
    float vA = accA * w3;
    float vB = accB * w3;
#pragma unroll
    for (int o = 16; o; o >>= 1) {
        vA += __shfl_down_sync(0xffffffffu, vA, o);
        vB += __shfl_down_sync(0xffffffffu, vB, o);
    }
    if (lane == 0) {
        out[e0] = vA + mb3[0];
        if (has2) out[e0 + 1] = vB + mb3[0];
    }
}

// ---------------- launch ----------------
extern "C" void kernel_launch(void* const* d_in, const int* in_sizes, int n_in,
                              void* d_out, int out_size) {
    const float* x = (const float*)d_in[0];
    const int* ei = (const int*)d_in[1];
    const float* ea = (const float*)d_in[2];
    const float* W1 = (const float*)d_in[3];
    const float* a1s = (const float*)d_in[4];
    const float* a1d = (const float*)d_in[5];
    const float* b1 = (const float*)d_in[6];
    const float* W2 = (const float*)d_in[7];
    const float* a2s = (const float*)d_in[8];
    const float* a2d = (const float*)d_in[9];
    const float* b2 = (const float*)d_in[10];
    const float* W3 = (const float*)d_in[11];
    const float* a3s = (const float*)d_in[12];
    const float* a3d = (const float*)d_in[13];
    const float* b3 = (const float*)d_in[14];
    const float* mw1 = (const float*)d_in[15];
    const float* mb1 = (const float*)d_in[16];
    const float* mw2 = (const float*)d_in[17];
    const float* mb2 = (const float*)d_in[18];
    const float* mw3 = (const float*)d_in[19];
    const float* mb3 = (const float*)d_in[20];
    float* out = (float*)d_out;

    int N = in_sizes[0] / 32;
    int E = in_sizes[1] / 2;

    int mBlocks = (N + 127) / 128;
    dim3 g256(4, mBlocks);
    dim3 g128(2, mBlocks);
    int alBlocks4 = ((N * 4) * 32 + 255) / 256;
    int alBlocks1 = ((N * 1) * 32 + 255) / 256;

    // 1) weight split into fragment table (once, tiny)
    wsplit_kernel<<<480, 256>>>(W1, W2, W3, mw1);
    // 2) zero degrees
    zero_deg_kernel<<<(N + 255) / 256, 256>>>(N);
    // 3) histogram
    hist_kernel<<<(E + 255) / 256, 256>>>(ei, E);
    // 4) layer-1 GEMM  <-- profiled slot (control)
    gemm_bf_kernel<0, 0><<<g256, 256>>>(x, FW1, 4, N, 32);
    // 5) scan
    scan_kernel<<<1, 1024>>>(N);
    // 6) scatter
    scatter_kernel<<<(E + 255) / 256, 256>>>(ei, E);
    // layer-1 attention + aggregation
    al_kernel<<<alBlocks4, 256>>>(a1s, a1d, N, 4, 64);
    agg_kernel<4, 64><<<N, 128>>>(b1, 1);

    // ---- layer 2 ----
    gemm_bf_kernel<1, 0><<<g256, 256>>>(x, FW2, 4, N, 256);
    al_kernel<<<alBlocks4, 256>>>(a2s, a2d, N, 4, 64);
    agg_kernel<4, 64><<<N, 128>>>(b2, 1);

    // ---- layer 3 ----
    gemm_bf_kernel<1, 0><<<g128, 256>>>(x, FW3, 2, N, 256);
    al_kernel<<<alBlocks1, 256>>>(a3s, a3d, N, 1, 128);
    agg_kernel<1, 128><<<N, 64>>>(b3, 0);

    // ---- edge MLP precompute (single combined GEMM) ----
    gemm_bf_kernel<1, 1><<<g128, 256>>>(x, FPC, 2, N, 128);

    // ---- edge MLP (2 edges per warp) ----
    int blocks = (E + 63) / 64;
    edge_mlp_kernel<<<blocks, 1024>>>(ei, ea, mw1, mb1, mw2, mb2, mw3, mb3, out, E);
}

// round 13
// speedup vs baseline: 1.0842x; 1.0842x over previous
#include <cuda_runtime.h>
#include <cuda_bf16.h>
#include <math.h>

// ---------------- problem constants ----------------
#define MAXN 50000
#define MAXE 800000
#define D12  256

// ---------------- scratch (device globals, compile-time symbol refs only) ---
__device__ float g_bufA[MAXN * D12];       // h (post-GEMM)
__device__ float g_bufB[MAXN * D12];       // aggregated output
__device__ unsigned g_Wf[122880];          // precomputed bf16 B-fragment table
__device__ float g_als[MAXN * 4];
__device__ float g_ald[MAXN * 4];
__device__ float g_pcomb[MAXN * 128];      // [prow | pcol] combined
__device__ int g_deg[MAXN];
__device__ int g_off[MAXN + 1];
__device__ int g_cur[MAXN];
__device__ int g_csr[MAXE];

// fragment-table offsets (words)
#define FW1   0        // 32*256   = 8192   (nBn=4, K=32)
#define FW2   8192     // 256*256  = 65536  (nBn=4, K=256)
#define FW3   73728    // 256*128  = 32768  (nBn=2, K=256)
#define FPC   106496   // 128*128  = 16384  (nBn=2, K=128, block-structured mw1)

__device__ __forceinline__ unsigned pack_bf16(float lo, float hi) {
    unsigned d;
    asm("cvt.rn.bf16x2.f32 %0, %1, %2;" : "=r"(d) : "f"(hi), "f"(lo));
    return d;
}

// ---------------- one-time weight split into mma fragment layout -----------
__global__ void wsplit_kernel(const float* W1, const float* W2, const float* W3,
                              const float* mw1) {
    int w = blockIdx.x * blockDim.x + threadIdx.x;
    if (w >= 122880) return;
    const float* src;
    int srcNc, nBn, rel, pcMode;
    if (w < 8192)        { src = W1;  srcNc = 256; nBn = 4; rel = w;          pcMode = 0; }
    else if (w < 73728)  { src = W2;  srcNc = 256; nBn = 4; rel = w - 8192;   pcMode = 0; }
    else if (w < 106496) { src = W3;  srcNc = 128; nBn = 2; rel = w - 73728;  pcMode = 0; }
    else                 { src = mw1; srcNc = 64;  nBn = 2; rel = w - 106496; pcMode = 1; }
    int tile = rel >> 10;
    int r = rel & 1023;
    int ni = r >> 7;
    int lane = (r >> 2) & 31;
    int sub = r & 3;
    int bs = sub >> 1, bw = sub & 1;
    int g = lane >> 2, tg = lane & 3;
    int bn = tile % nBn, t = tile / nBn;
    int P = tg + bw * 4;
    int colWithin = ni * 8 + g;
    int col = pcMode ? colWithin : (bn * 64 + colWithin);
    int k = (pcMode ? bn * 128 : 0) + t * 16 + 2 * P;
    float x0 = src[k * srcNc + col];
    float x1 = src[(k + 1) * srcNc + col];
    unsigned big = pack_bf16(x0, x1);
    float lo = __uint_as_float(big << 16);
    float hi = __uint_as_float(big & 0xffff0000u);
    unsigned sml = pack_bf16(x0 - lo, x1 - hi);
    g_Wf[w] = bs ? sml : big;
}

// ---------------- CSR construction ----------------
__global__ void zero_deg_kernel(int n) {
    int i = blockIdx.x * blockDim.x + threadIdx.x;
    if (i < n) g_deg[i] = 0;
}

__global__ void hist_kernel(const int* ei, int E) {
    int i = blockIdx.x * blockDim.x + threadIdx.x;
    if (i < E) atomicAdd(&g_deg[ei[E + i]], 1);
}

// warp-shuffle block scan: 1024 threads, each owns a contiguous run.
__global__ void scan_kernel(int n) {
    __shared__ int warpsum[32];
    int tid = threadIdx.x;
    int per = (n + 1023) >> 10;
    int start = tid * per;
    int end = min(start + per, n);
    int s = 0;
    for (int i = start; i < end; i++) s += g_deg[i];

    int lane = tid & 31, wid = tid >> 5;
    int incl = s;
#pragma unroll
    for (int o = 1; o < 32; o <<= 1) {
        int v = __shfl_up_sync(0xffffffffu, incl, o);
        if (lane >= o) incl += v;
    }
    if (lane == 31) warpsum[wid] = incl;
    __syncthreads();
    if (wid == 0) {
        int w = warpsum[lane];
        int wi = w;
#pragma unroll
        for (int o = 1; o < 32; o <<= 1) {
            int v = __shfl_up_sync(0xffffffffu, wi, o);
            if (lane >= o) wi += v;
        }
        warpsum[lane] = wi - w;
    }
    __syncthreads();
    int run = (incl - s) + warpsum[wid];
    for (int i = start; i < end; i++) {
        int d = g_deg[i];
        g_off[i] = run;
        g_cur[i] = run;
        run += d;
    }
    if (tid == 1023) g_off[n] = run;
}

__global__ void scatter_kernel(const int* ei, int E) {
    int i = blockIdx.x * blockDim.x + threadIdx.x;
    if (i < E) {
        int d = ei[E + i];
        int s = ei[i];
        int p = atomicAdd(&g_cur[d], 1);
        g_csr[p] = s;
    }
}

// zero g_als/g_ald (layer-3 atomic accumulation needs clean slate)
__global__ void zero_al_kernel(int n) {
    int i = blockIdx.x * blockDim.x + threadIdx.x;
    if (i < n) { g_als[i] = 0.f; g_ald[i] = 0.f; }
}

// ---------------- 3-term bf16 tensor-core GEMM + fused attention dots ------
// C[M,Nc] = A @ B; B frags from g_Wf; A split in-kernel.
// ALF: 0 = none; 1 = direct store g_als/g_ald[row*4+bn]; 2 = atomicAdd (H=1).
__device__ __forceinline__ void mma_bf16(float& d0, float& d1, float& d2, float& d3,
                                         unsigned a0, unsigned a1, unsigned a2, unsigned a3,
                                         unsigned b0, unsigned b1) {
    asm volatile(
        "mma.sync.aligned.m16n8k16.row.col.f32.bf16.bf16.f32 "
        "{%0,%1,%2,%3}, {%4,%5,%6,%7}, {%8,%9}, {%0,%1,%2,%3};"
        : "+f"(d0), "+f"(d1), "+f"(d2), "+f"(d3)
        : "r"(a0), "r"(a1), "r"(a2), "r"(a3), "r"(b0), "r"(b1));
}

template <int ASRC, int CSEL, int ALF>
__global__ void __launch_bounds__(256) gemm_bf_kernel(const float* Aext,
                                                      const float* as, const float* ad,
                                                      int fbase, int nBn, int M, int K) {
    const float* A;
    if constexpr (ASRC == 0) A = Aext; else A = (const float*)g_bufB;
    float* C;
    if constexpr (CSEL == 0) C = g_bufA; else C = g_pcomb;
    int Nc = nBn * 64;

    __shared__ unsigned sAb[2][1024];
    __shared__ unsigned sAs[2][1024];
    __shared__ float sh_s1[128];
    __shared__ float sh_s2[128];

    int tid = threadIdx.x;
    int bm = blockIdx.y * 128;
    int bn = blockIdx.x;
    int warpId = tid >> 5;
    int lane = tid & 31;
    int g = lane >> 2;
    int tg = lane & 3;
    int wCol = (warpId >> 2) * 32;
    int wTile0 = (warpId & 3) * 2;

    int ar = tid >> 1;
    int khalf = tid & 1;
    int att = ar >> 4;
    int asub = ar & 15;
    int ahi = asub >> 3;
    int agg = asub & 7;

    if (ALF > 0 && tid < 128) { sh_s1[tid] = 0.f; sh_s2[tid] = 0.f; }

    float d[2][4][4];
#pragma unroll
    for (int mi = 0; mi < 2; mi++)
#pragma unroll
        for (int ni = 0; ni < 4; ni++)
#pragma unroll
            for (int q = 0; q < 4; q++) d[mi][ni][q] = 0.f;

    const unsigned* Wf = (const unsigned*)g_Wf;
    int p = 0;

    for (int k0 = 0; k0 < K; k0 += 16, p ^= 1) {
        int t = k0 >> 4;
        uint4 bfr[4];
        {
            const uint4* fb = (const uint4*)(Wf + fbase + (size_t)(t * nBn + bn) * 1024);
#pragma unroll
            for (int nj = 0; nj < 4; nj++)
                bfr[nj] = fb[((wCol >> 3) + nj) * 32 + lane];
        }
        {
            float4 v0 = make_float4(0.f, 0.f, 0.f, 0.f);
            float4 v1 = make_float4(0.f, 0.f, 0.f, 0.f);
            if (bm + ar < M) {
                const float* pp = A + (size_t)(bm + ar) * K + k0 + khalf * 8;
                v0 = *(const float4*)pp;
                v1 = *(const float4*)(pp + 4);
            }
            float xs[8] = {v0.x, v0.y, v0.z, v0.w, v1.x, v1.y, v1.z, v1.w};
#pragma unroll
            for (int p2 = 0; p2 < 4; p2++) {
                int wsl = khalf * 2 + ahi;
                int slot = p2 ^ ((agg >> 1) & 3);
                int idx = att * 128 + (agg * 4 + slot) * 4 + wsl;
                unsigned big = pack_bf16(xs[2 * p2], xs[2 * p2 + 1]);
                float lo = __uint_as_float(big << 16);
                float hi = __uint_as_float(big & 0xffff0000u);
                sAb[p][idx] = big;
                sAs[p][idx] = pack_bf16(xs[2 * p2] - lo, xs[2 * p2 + 1] - hi);
            }
        }
        __syncthreads();

        uint4 afb[2], afs[2];
#pragma unroll
        for (int mi = 0; mi < 2; mi++) {
            int base = (wTile0 + mi) * 128 + (g * 4 + (tg ^ ((g >> 1) & 3))) * 4;
            afb[mi] = *(const uint4*)&sAb[p][base];
            afs[mi] = *(const uint4*)&sAs[p][base];
        }

#pragma unroll
        for (int ni = 0; ni < 4; ni++) {
            uint4 b = bfr[ni];
#pragma unroll
            for (int mi = 0; mi < 2; mi++) {
                float* dd = d[mi][ni];
                mma_bf16(dd[0], dd[1], dd[2], dd[3],
                         afb[mi].x, afb[mi].y, afb[mi].z, afb[mi].w, b.x, b.y);
                mma_bf16(dd[0], dd[1], dd[2], dd[3],
                         afb[mi].x, afb[mi].y, afb[mi].z, afb[mi].w, b.z, b.w);
                mma_bf16(dd[0], dd[1], dd[2], dd[3],
                         afs[mi].x, afs[mi].y, afs[mi].z, afs[mi].w, b.x, b.y);
            }
        }
    }

    // ---- epilogue: C stores (+ fused attention dot-products) ----
#pragma unroll
    for (int mi = 0; mi < 2; mi++) {
#pragma unroll
        for (int ni = 0; ni < 4; ni++) {
            int row0 = bm + (wTile0 + mi) * 16 + g;
            int col = bn * 64 + wCol + ni * 8 + tg * 2;
            if (row0 < M)
                *(float2*)(C + (size_t)row0 * Nc + col) = make_float2(d[mi][ni][0], d[mi][ni][1]);
            if (row0 + 8 < M)
                *(float2*)(C + (size_t)(row0 + 8) * Nc + col) = make_float2(d[mi][ni][2], d[mi][ni][3]);
        }
    }
    if constexpr (ALF > 0) {
        float p1[2][2] = {{0.f, 0.f}, {0.f, 0.f}};
        float p2[2][2] = {{0.f, 0.f}, {0.f, 0.f}};
#pragma unroll
        for (int ni = 0; ni < 4; ni++) {
            int col = bn * 64 + wCol + ni * 8 + tg * 2;
            float a0 = as[col], a1 = as[col + 1];
            float b0 = ad[col], b1 = ad[col + 1];
#pragma unroll
            for (int mi = 0; mi < 2; mi++) {
                p1[mi][0] += d[mi][ni][0] * a0 + d[mi][ni][1] * a1;
                p1[mi][1] += d[mi][ni][2] * a0 + d[mi][ni][3] * a1;
                p2[mi][0] += d[mi][ni][0] * b0 + d[mi][ni][1] * b1;
                p2[mi][1] += d[mi][ni][2] * b0 + d[mi][ni][3] * b1;
            }
        }
        // reduce over tg (width-4 segments)
#pragma unroll
        for (int o = 2; o >= 1; o >>= 1) {
#pragma unroll
            for (int mi = 0; mi < 2; mi++)
#pragma unroll
                for (int hh = 0; hh < 2; hh++) {
                    p1[mi][hh] += __shfl_down_sync(0xffffffffu, p1[mi][hh], o, 4);
                    p2[mi][hh] += __shfl_down_sync(0xffffffffu, p2[mi][hh], o, 4);
                }
        }
        if (tg == 0) {
#pragma unroll
            for (int mi = 0; mi < 2; mi++)
#pragma unroll
                for (int hh = 0; hh < 2; hh++) {
                    int rl = (wTile0 + mi) * 16 + g + hh * 8;
                    atomicAdd(&sh_s1[rl], p1[mi][hh]);
                    atomicAdd(&sh_s2[rl], p2[mi][hh]);
                }
        }
        __syncthreads();
        if (tid < 128) {
            int row = bm + tid;
            if (row < M) {
                if constexpr (ALF == 1) {
                    g_als[row * 4 + bn] = sh_s1[tid];
                    g_ald[row * 4 + bn] = sh_s2[tid];
                } else {
                    atomicAdd(&g_als[row], sh_s1[tid]);
                    atomicAdd(&g_ald[row], sh_s2[tid]);
                }
            }
        }
    }
}

// ---------------- GAT aggregation (two-pass, R11 form): bufA -> bufB -------
template <int H, int C>
__global__ void agg_kernel(const float* bias, int applyElu) {
    const int D2 = H * C / 2;
    const int CHUNK = (H == 4) ? 32 : 64;
    int n = blockIdx.x;
    int t = threadIdx.x;
    __shared__ float sh_m[H];
    __shared__ float sh_iz[H];
    __shared__ float sh_ad[H];
    __shared__ float sh_alpha[CHUNK * H];
    __shared__ int sh_src[CHUNK];

    int o0 = g_off[n];
    int deg = g_off[n + 1] - o0;
    int wid = t >> 5, lane = t & 31;

    if (wid < H) {
        int hd = wid;
        float adn = g_ald[n * H + hd];
        float m = -1e30f, s = 0.f;
        for (int j = lane; j <= deg; j += 32) {
            int src = (j < deg) ? g_csr[o0 + j] : n;
            float att = g_als[src * H + hd] + adn;
            att = att > 0.f ? att : 0.2f * att;
            float mn = fmaxf(m, att);
            s = s * __expf(m - mn) + __expf(att - mn);
            m = mn;
        }
#pragma unroll
        for (int o = 16; o; o >>= 1) {
            float m2 = __shfl_down_sync(0xffffffffu, m, o);
            float s2 = __shfl_down_sync(0xffffffffu, s, o);
            float mn = fmaxf(m, m2);
            s = s * __expf(m - mn) + s2 * __expf(m2 - mn);
            m = mn;
        }
        if (lane == 0) {
            sh_m[hd] = m;
            sh_iz[hd] = 1.0f / s;
            sh_ad[hd] = adn;
        }
    }
    __syncthreads();

    int head = t / (C / 2);
    float2 acc = make_float2(0.f, 0.f);
    int total = deg + 1;
    const float2* h2 = (const float2*)g_bufA;
    for (int base = 0; base < total; base += CHUNK) {
        int cnt = min(CHUNK, total - base);
        {
            int j = t / H;
            int hd = t % H;
            if (j < cnt) {
                int src = (base + j < deg) ? g_csr[o0 + base + j] : n;
                if (hd == 0) sh_src[j] = src;
                float att = g_als[src * H + hd] + sh_ad[hd];
                att = att > 0.f ? att : 0.2f * att;
                sh_alpha[j * H + hd] = __expf(att - sh_m[hd]) * sh_iz[hd];
            }
        }
        __syncthreads();
#pragma unroll 4
        for (int j = 0; j < cnt; j++) {
            float2 v = h2[(size_t)sh_src[j] * D2 + t];
            float a = sh_alpha[j * H + head];
            acc.x = fmaf(v.x, a, acc.x);
            acc.y = fmaf(v.y, a, acc.y);
        }
        __syncthreads();
    }
    float rx = acc.x + bias[2 * t];
    float ry = acc.y + bias[2 * t + 1];
    if (applyElu) {
        rx = rx > 0.f ? rx : expm1f(rx);
        ry = ry > 0.f ? ry : expm1f(ry);
    }
    *(float2*)(g_bufB + (size_t)n * (2 * D2) + 2 * t) = make_float2(rx, ry);
}

// ---------------- edge MLP: 2 edges per warp, float2-packed sw2 ------------
__global__ void __launch_bounds__(1024) edge_mlp_kernel(const int* ei, const float* ea,
                                const float* mw1, const float* mb1,
                                const float* mw2, const float* mb2,
                                const float* mw3, const float* mb3,
                                float* out, int E) {
    __shared__ float2 sw2t[1024];
    int tid = threadIdx.x;
    {
        int sl = tid >> 5, ln = tid & 31;
        sw2t[tid] = make_float2(mw2[sl * 64 + ln], mw2[sl * 64 + 32 + ln]);
    }
    __syncthreads();

    int warp = (int)((blockIdx.x * (size_t)blockDim.x + tid) >> 5);
    int lane = tid & 31;
    int e0 = warp * 2;
    if (e0 >= E) return;
    bool has2 = (e0 + 1 < E);
    int e1 = has2 ? e0 + 1 : e0;

    int rowA = ei[e0], colA = ei[E + e0];
    int rowB = ei[e1], colB = ei[E + e1];
    float eaA0 = ea[e0 * 2], eaA1 = ea[e0 * 2 + 1];
    float eaB0 = ea[e1 * 2], eaB1 = ea[e1 * 2 + 1];

    int j0 = lane * 2;
    float w1e0 = mw1[256 * 64 + j0], w1e0b = mw1[256 * 64 + j0 + 1];
    float w1e1 = mw1[257 * 64 + j0], w1e1b = mw1[257 * 64 + j0 + 1];
    float bj0 = mb1[j0], bj1 = mb1[j0 + 1];

    float2 prA = *(const float2*)(g_pcomb + (size_t)rowA * 128 + j0);
    float2 pcA = *(const float2*)(g_pcomb + (size_t)colA * 128 + 64 + j0);
    float2 prB = *(const float2*)(g_pcomb + (size_t)rowB * 128 + j0);
    float2 pcB = *(const float2*)(g_pcomb + (size_t)colB * 128 + 64 + j0);

    float o1aA = fmaxf(prA.x + pcA.x + eaA0 * w1e0 + eaA1 * w1e1 + bj0, 0.f);
    float o1bA = fmaxf(prA.y + pcA.y + eaA0 * w1e0b + eaA1 * w1e1b + bj1, 0.f);
    float o1aB = fmaxf(prB.x + pcB.x + eaB0 * w1e0 + eaB1 * w1e1 + bj0, 0.f);
    float o1bB = fmaxf(prB.y + pcB.y + eaB0 * w1e0b + eaB1 * w1e1b + bj1, 0.f);

    float accA = mb2[lane];
    float accB = accA;
#pragma unroll
    for (int sl = 0; sl < 32; sl++) {
        float2 w = sw2t[sl * 32 + lane];
        float vaA = __shfl_sync(0xffffffffu, o1aA, sl);
        float vbA = __shfl_sync(0xffffffffu, o1bA, sl);
        float vaB = __shfl_sync(0xffffffffu, o1aB, sl);
        float vbB = __shfl_sync(0xffffffffu, o1bB, sl);
        accA = fmaf(vaA, w.x, accA);
        accA = fmaf(vbA, w.y, accA);
        accB = fmaf(vaB, w.x, accB);
        accB = fmaf(vbB, w.y, accB);
    }
    accA = fmaxf(accA, 0.f);
    accB = fmaxf(accB, 0.f);

    float w3 = mw3[lane];
    float vA = accA * w3;
    float vB = accB * w3;
#pragma unroll
    for (int o = 16; o; o >>= 1) {
        vA += __shfl_down_sync(0xffffffffu, vA, o);
        vB += __shfl_down_sync(0xffffffffu, vB, o);
    }
    if (lane == 0) {
        out[e0] = vA + mb3[0];
        if (has2) out[e0 + 1] = vB + mb3[0];
    }
}

// ---------------- launch ----------------
extern "C" void kernel_launch(void* const* d_in, const int* in_sizes, int n_in,
                              void* d_out, int out_size) {
    const float* x = (const float*)d_in[0];
    const int* ei = (const int*)d_in[1];
    const float* ea = (const float*)d_in[2];
    const float* W1 = (const float*)d_in[3];
    const float* a1s = (const float*)d_in[4];
    const float* a1d = (const float*)d_in[5];
    const float* b1 = (const float*)d_in[6];
    const float* W2 = (const float*)d_in[7];
    const float* a2s = (const float*)d_in[8];
    const float* a2d = (const float*)d_in[9];
    const float* b2 = (const float*)d_in[10];
    const float* W3 = (const float*)d_in[11];
    const float* a3s = (const float*)d_in[12];
    const float* a3d = (const float*)d_in[13];
    const float* b3 = (const float*)d_in[14];
    const float* mw1 = (const float*)d_in[15];
    const float* mb1 = (const float*)d_in[16];
    const float* mw2 = (const float*)d_in[17];
    const float* mb2 = (const float*)d_in[18];
    const float* mw3 = (const float*)d_in[19];
    const float* mb3 = (const float*)d_in[20];
    float* out = (float*)d_out;

    int N = in_sizes[0] / 32;
    int E = in_sizes[1] / 2;

    int mBlocks = (N + 127) / 128;
    dim3 g256(4, mBlocks);
    dim3 g128(2, mBlocks);

    // 1) weight split into fragment table (once, tiny)
    wsplit_kernel<<<480, 256>>>(W1, W2, W3, mw1);
    // 2) zero degrees
    zero_deg_kernel<<<(N + 255) / 256, 256>>>(N);
    // 3) histogram
    hist_kernel<<<(E + 255) / 256, 256>>>(ei, E);
    // 4) layer-1 GEMM with fused attention dots  <-- profiled slot
    gemm_bf_kernel<0, 0, 1><<<g256, 256>>>(x, a1s, a1d, FW1, 4, N, 32);
    // 5) scan
    scan_kernel<<<1, 1024>>>(N);
    // 6) scatter
    scatter_kernel<<<(E + 255) / 256, 256>>>(ei, E);
    // layer-1 aggregation
    agg_kernel<4, 64><<<N, 128>>>(b1, 1);

    // ---- layer 2 ----
    gemm_bf_kernel<1, 0, 1><<<g256, 256>>>(x, a2s, a2d, FW2, 4, N, 256);
    agg_kernel<4, 64><<<N, 128>>>(b2, 1);

    // ---- layer 3 (atomic al accumulation; zero first) ----
    zero_al_kernel<<<(N + 255) / 256, 256>>>(N);
    gemm_bf_kernel<1, 0, 2><<<g128, 256>>>(x, a3s, a3d, FW3, 2, N, 256);
    agg_kernel<1, 128><<<N, 64>>>(b3, 0);

    // ---- edge MLP precompute (single combined GEMM, no fusion) ----
    gemm_bf_kernel<1, 1, 0><<<g128, 256>>>(x, a1s, a1d, FPC, 2, N, 128);

    // ---- edge MLP (2 edges per warp) ----
    int blocks = (E + 63) / 64;
    edge_mlp_kernel<<<blocks, 1024>>>(ei, ea, mw1, mb1, mw2, mb2, mw3, mb3, out, E);
}

// round 14
// speedup vs baseline: 1.5569x; 1.4359x over previous
#include <cuda_runtime.h>
#include <cuda_bf16.h>
#include <math.h>

// ---------------- problem constants ----------------
#define MAXN 50000
#define MAXE 800000
#define D12  256

// ---------------- scratch ----------------
__device__ float g_bufA[MAXN * D12];
__device__ float g_bufB[MAXN * D12];
__device__ unsigned g_Wf[124928];          // bf16 fragment tables (weights + mw2)
__device__ float g_als[MAXN * 4];
__device__ float g_ald[MAXN * 4];
__device__ float g_pcomb[MAXN * 128];
__device__ int g_deg[MAXN];
__device__ int g_off[MAXN + 1];
__device__ int g_cur[MAXN];
__device__ int g_csr[MAXE];

// fragment-table offsets (words)
#define FW1   0        // 32*256
#define FW2   8192     // 256*256
#define FW3   73728    // 256*128
#define FPC   106496   // 128*128 (block-structured mw1)
#define FM2   122880   // 64*32 (edge-MLP layer 2), 2048 words

__device__ __forceinline__ unsigned pack_bf16(float lo, float hi) {
    unsigned d;
    asm("cvt.rn.bf16x2.f32 %0, %1, %2;" : "=r"(d) : "f"(hi), "f"(lo));
    return d;
}

// ---------------- one-time weight split into mma fragment layout -----------
__global__ void wsplit_kernel(const float* W1, const float* W2, const float* W3,
                              const float* mw1, const float* mw2) {
    int w = blockIdx.x * blockDim.x + threadIdx.x;
    if (w >= 124928) return;
    if (w >= 122880) {
        // mw2 region: word = FM2 + (t*4+ni)*128 + lane*4 + sub
        int rel = w - 122880;
        int sub = rel & 3;
        int lane = (rel >> 2) & 31;
        int ni = (rel >> 7) & 3;
        int t = rel >> 9;
        int bs = sub >> 1, bw = sub & 1;
        int g = lane >> 2, tg = lane & 3;
        int col = ni * 8 + g;
        int k = t * 16 + 2 * (tg + bw * 4);
        float x0 = mw2[k * 32 + col];
        float x1 = mw2[(k + 1) * 32 + col];
        unsigned big = pack_bf16(x0, x1);
        float lo = __uint_as_float(big << 16);
        float hi = __uint_as_float(big & 0xffff0000u);
        unsigned sml = pack_bf16(x0 - lo, x1 - hi);
        g_Wf[w] = bs ? sml : big;
        return;
    }
    const float* src;
    int srcNc, nBn, rel, pcMode;
    if (w < 8192)        { src = W1;  srcNc = 256; nBn = 4; rel = w;          pcMode = 0; }
    else if (w < 73728)  { src = W2;  srcNc = 256; nBn = 4; rel = w - 8192;   pcMode = 0; }
    else if (w < 106496) { src = W3;  srcNc = 128; nBn = 2; rel = w - 73728;  pcMode = 0; }
    else                 { src = mw1; srcNc = 64;  nBn = 2; rel = w - 106496; pcMode = 1; }
    int tile = rel >> 10;
    int r = rel & 1023;
    int ni = r >> 7;
    int lane = (r >> 2) & 31;
    int sub = r & 3;
    int bs = sub >> 1, bw = sub & 1;
    int g = lane >> 2, tg = lane & 3;
    int bn = tile % nBn, t = tile / nBn;
    int P = tg + bw * 4;
    int colWithin = ni * 8 + g;
    int col = pcMode ? colWithin : (bn * 64 + colWithin);
    int k = (pcMode ? bn * 128 : 0) + t * 16 + 2 * P;
    float x0 = src[k * srcNc + col];
    float x1 = src[(k + 1) * srcNc + col];
    unsigned big = pack_bf16(x0, x1);
    float lo = __uint_as_float(big << 16);
    float hi = __uint_as_float(big & 0xffff0000u);
    unsigned sml = pack_bf16(x0 - lo, x1 - hi);
    g_Wf[w] = bs ? sml : big;
}

// ---------------- CSR construction ----------------
__global__ void zero_deg_kernel(int n) {
    int i = blockIdx.x * blockDim.x + threadIdx.x;
    if (i < n) g_deg[i] = 0;
}

__global__ void hist_kernel(const int* ei, int E) {
    int i = blockIdx.x * blockDim.x + threadIdx.x;
    if (i < E) atomicAdd(&g_deg[ei[E + i]], 1);
}

__global__ void scan_kernel(int n) {
    __shared__ int warpsum[32];
    int tid = threadIdx.x;
    int per = (n + 1023) >> 10;
    int start = tid * per;
    int end = min(start + per, n);
    int s = 0;
    for (int i = start; i < end; i++) s += g_deg[i];

    int lane = tid & 31, wid = tid >> 5;
    int incl = s;
#pragma unroll
    for (int o = 1; o < 32; o <<= 1) {
        int v = __shfl_up_sync(0xffffffffu, incl, o);
        if (lane >= o) incl += v;
    }
    if (lane == 31) warpsum[wid] = incl;
    __syncthreads();
    if (wid == 0) {
        int w = warpsum[lane];
        int wi = w;
#pragma unroll
        for (int o = 1; o < 32; o <<= 1) {
            int v = __shfl_up_sync(0xffffffffu, wi, o);
            if (lane >= o) wi += v;
        }
        warpsum[lane] = wi - w;
    }
    __syncthreads();
    int run = (incl - s) + warpsum[wid];
    for (int i = start; i < end; i++) {
        int d = g_deg[i];
        g_off[i] = run;
        g_cur[i] = run;
        run += d;
    }
    if (tid == 1023) g_off[n] = run;
}

__global__ void scatter_kernel(const int* ei, int E) {
    int i = blockIdx.x * blockDim.x + threadIdx.x;
    if (i < E) {
        int d = ei[E + i];
        int s = ei[i];
        int p = atomicAdd(&g_cur[d], 1);
        g_csr[p] = s;
    }
}

__global__ void zero_al_kernel(int n) {
    int i = blockIdx.x * blockDim.x + threadIdx.x;
    if (i < n) { g_als[i] = 0.f; g_ald[i] = 0.f; }
}

// ---------------- 3-term bf16 tensor-core GEMM + fused attention dots ------
__device__ __forceinline__ void mma_bf16(float& d0, float& d1, float& d2, float& d3,
                                         unsigned a0, unsigned a1, unsigned a2, unsigned a3,
                                         unsigned b0, unsigned b1) {
    asm volatile(
        "mma.sync.aligned.m16n8k16.row.col.f32.bf16.bf16.f32 "
        "{%0,%1,%2,%3}, {%4,%5,%6,%7}, {%8,%9}, {%0,%1,%2,%3};"
        : "+f"(d0), "+f"(d1), "+f"(d2), "+f"(d3)
        : "r"(a0), "r"(a1), "r"(a2), "r"(a3), "r"(b0), "r"(b1));
}

template <int ASRC, int CSEL, int ALF>
__global__ void __launch_bounds__(256) gemm_bf_kernel(const float* Aext,
                                                      const float* as, const float* ad,
                                                      int fbase, int nBn, int M, int K) {
    const float* A;
    if constexpr (ASRC == 0) A = Aext; else A = (const float*)g_bufB;
    float* C;
    if constexpr (CSEL == 0) C = g_bufA; else C = g_pcomb;
    int Nc = nBn * 64;

    __shared__ unsigned sAb[2][1024];
    __shared__ unsigned sAs[2][1024];
    __shared__ float sh_s1[128];
    __shared__ float sh_s2[128];

    int tid = threadIdx.x;
    int bm = blockIdx.y * 128;
    int bn = blockIdx.x;
    int warpId = tid >> 5;
    int lane = tid & 31;
    int g = lane >> 2;
    int tg = lane & 3;
    int wCol = (warpId >> 2) * 32;
    int wTile0 = (warpId & 3) * 2;

    int ar = tid >> 1;
    int khalf = tid & 1;
    int att = ar >> 4;
    int asub = ar & 15;
    int ahi = asub >> 3;
    int agg = asub & 7;

    if (ALF > 0 && tid < 128) { sh_s1[tid] = 0.f; sh_s2[tid] = 0.f; }

    float d[2][4][4];
#pragma unroll
    for (int mi = 0; mi < 2; mi++)
#pragma unroll
        for (int ni = 0; ni < 4; ni++)
#pragma unroll
            for (int q = 0; q < 4; q++) d[mi][ni][q] = 0.f;

    const unsigned* Wf = (const unsigned*)g_Wf;
    int p = 0;

    for (int k0 = 0; k0 < K; k0 += 16, p ^= 1) {
        int t = k0 >> 4;
        uint4 bfr[4];
        {
            const uint4* fb = (const uint4*)(Wf + fbase + (size_t)(t * nBn + bn) * 1024);
#pragma unroll
            for (int nj = 0; nj < 4; nj++)
                bfr[nj] = fb[((wCol >> 3) + nj) * 32 + lane];
        }
        {
            float4 v0 = make_float4(0.f, 0.f, 0.f, 0.f);
            float4 v1 = make_float4(0.f, 0.f, 0.f, 0.f);
            if (bm + ar < M) {
                const float* pp = A + (size_t)(bm + ar) * K + k0 + khalf * 8;
                v0 = *(const float4*)pp;
                v1 = *(const float4*)(pp + 4);
            }
            float xs[8] = {v0.x, v0.y, v0.z, v0.w, v1.x, v1.y, v1.z, v1.w};
#pragma unroll
            for (int p2 = 0; p2 < 4; p2++) {
                int wsl = khalf * 2 + ahi;
                int slot = p2 ^ ((agg >> 1) & 3);
                int idx = att * 128 + (agg * 4 + slot) * 4 + wsl;
                unsigned big = pack_bf16(xs[2 * p2], xs[2 * p2 + 1]);
                float lo = __uint_as_float(big << 16);
                float hi = __uint_as_float(big & 0xffff0000u);
                sAb[p][idx] = big;
                sAs[p][idx] = pack_bf16(xs[2 * p2] - lo, xs[2 * p2 + 1] - hi);
            }
        }
        __syncthreads();

        uint4 afb[2], afs[2];
#pragma unroll
        for (int mi = 0; mi < 2; mi++) {
            int base = (wTile0 + mi) * 128 + (g * 4 + (tg ^ ((g >> 1) & 3))) * 4;
            afb[mi] = *(const uint4*)&sAb[p][base];
            afs[mi] = *(const uint4*)&sAs[p][base];
        }

#pragma unroll
        for (int ni = 0; ni < 4; ni++) {
            uint4 b = bfr[ni];
#pragma unroll
            for (int mi = 0; mi < 2; mi++) {
                float* dd = d[mi][ni];
                mma_bf16(dd[0], dd[1], dd[2], dd[3],
                         afb[mi].x, afb[mi].y, afb[mi].z, afb[mi].w, b.x, b.y);
                mma_bf16(dd[0], dd[1], dd[2], dd[3],
                         afb[mi].x, afb[mi].y, afb[mi].z, afb[mi].w, b.z, b.w);
                mma_bf16(dd[0], dd[1], dd[2], dd[3],
                         afs[mi].x, afs[mi].y, afs[mi].z, afs[mi].w, b.x, b.y);
            }
        }
    }

#pragma unroll
    for (int mi = 0; mi < 2; mi++) {
#pragma unroll
        for (int ni = 0; ni < 4; ni++) {
            int row0 = bm + (wTile0 + mi) * 16 + g;
            int col = bn * 64 + wCol + ni * 8 + tg * 2;
            if (row0 < M)
                *(float2*)(C + (size_t)row0 * Nc + col) = make_float2(d[mi][ni][0], d[mi][ni][1]);
            if (row0 + 8 < M)
                *(float2*)(C + (size_t)(row0 + 8) * Nc + col) = make_float2(d[mi][ni][2], d[mi][ni][3]);
        }
    }
    if constexpr (ALF > 0) {
        float p1[2][2] = {{0.f, 0.f}, {0.f, 0.f}};
        float p2[2][2] = {{0.f, 0.f}, {0.f, 0.f}};
#pragma unroll
        for (int ni = 0; ni < 4; ni++) {
            int col = bn * 64 + wCol + ni * 8 + tg * 2;
            float a0 = as[col], a1 = as[col + 1];
            float b0 = ad[col], b1 = ad[col + 1];
#pragma unroll
            for (int mi = 0; mi < 2; mi++) {
                p1[mi][0] += d[mi][ni][0] * a0 + d[mi][ni][1] * a1;
                p1[mi][1] += d[mi][ni][2] * a0 + d[mi][ni][3] * a1;
                p2[mi][0] += d[mi][ni][0] * b0 + d[mi][ni][1] * b1;
                p2[mi][1] += d[mi][ni][2] * b0 + d[mi][ni][3] * b1;
            }
        }
#pragma unroll
        for (int o = 2; o >= 1; o >>= 1) {
#pragma unroll
            for (int mi = 0; mi < 2; mi++)
#pragma unroll
                for (int hh = 0; hh < 2; hh++) {
                    p1[mi][hh] += __shfl_down_sync(0xffffffffu, p1[mi][hh], o, 4);
                    p2[mi][hh] += __shfl_down_sync(0xffffffffu, p2[mi][hh], o, 4);
                }
        }
        if (tg == 0) {
#pragma unroll
            for (int mi = 0; mi < 2; mi++)
#pragma unroll
                for (int hh = 0; hh < 2; hh++) {
                    int rl = (wTile0 + mi) * 16 + g + hh * 8;
                    atomicAdd(&sh_s1[rl], p1[mi][hh]);
                    atomicAdd(&sh_s2[rl], p2[mi][hh]);
                }
        }
        __syncthreads();
        if (tid < 128) {
            int row = bm + tid;
            if (row < M) {
                if constexpr (ALF == 1) {
                    g_als[row * 4 + bn] = sh_s1[tid];
                    g_ald[row * 4 + bn] = sh_s2[tid];
                } else {
                    atomicAdd(&g_als[row], sh_s1[tid]);
                    atomicAdd(&g_ald[row], sh_s2[tid]);
                }
            }
        }
    }
}

// ---------------- GAT aggregation (two-pass): bufA -> bufB ----------------
template <int H, int C>
__global__ void agg_kernel(const float* bias, int applyElu) {
    const int D2 = H * C / 2;
    const int CHUNK = (H == 4) ? 32 : 64;
    int n = blockIdx.x;
    int t = threadIdx.x;
    __shared__ float sh_m[H];
    __shared__ float sh_iz[H];
    __shared__ float sh_ad[H];
    __shared__ float sh_alpha[CHUNK * H];
    __shared__ int sh_src[CHUNK];

    int o0 = g_off[n];
    int deg = g_off[n + 1] - o0;
    int wid = t >> 5, lane = t & 31;

    if (wid < H) {
        int hd = wid;
        float adn = g_ald[n * H + hd];
        float m = -1e30f, s = 0.f;
        for (int j = lane; j <= deg; j += 32) {
            int src = (j < deg) ? g_csr[o0 + j] : n;
            float att = g_als[src * H + hd] + adn;
            att = att > 0.f ? att : 0.2f * att;
            float mn = fmaxf(m, att);
            s = s * __expf(m - mn) + __expf(att - mn);
            m = mn;
        }
#pragma unroll
        for (int o = 16; o; o >>= 1) {
            float m2 = __shfl_down_sync(0xffffffffu, m, o);
            float s2 = __shfl_down_sync(0xffffffffu, s, o);
            float mn = fmaxf(m, m2);
            s = s * __expf(m - mn) + s2 * __expf(m2 - mn);
            m = mn;
        }
        if (lane == 0) {
            sh_m[hd] = m;
            sh_iz[hd] = 1.0f / s;
            sh_ad[hd] = adn;
        }
    }
    __syncthreads();

    int head = t / (C / 2);
    float2 acc = make_float2(0.f, 0.f);
    int total = deg + 1;
    const float2* h2 = (const float2*)g_bufA;
    for (int base = 0; base < total; base += CHUNK) {
        int cnt = min(CHUNK, total - base);
        {
            int j = t / H;
            int hd = t % H;
            if (j < cnt) {
                int src = (base + j < deg) ? g_csr[o0 + base + j] : n;
                if (hd == 0) sh_src[j] = src;
                float att = g_als[src * H + hd] + sh_ad[hd];
                att = att > 0.f ? att : 0.2f * att;
                sh_alpha[j * H + hd] = __expf(att - sh_m[hd]) * sh_iz[hd];
            }
        }
        __syncthreads();
#pragma unroll 4
        for (int j = 0; j < cnt; j++) {
            float2 v = h2[(size_t)sh_src[j] * D2 + t];
            float a = sh_alpha[j * H + head];
            acc.x = fmaf(v.x, a, acc.x);
            acc.y = fmaf(v.y, a, acc.y);
        }
        __syncthreads();
    }
    float rx = acc.x + bias[2 * t];
    float ry = acc.y + bias[2 * t + 1];
    if (applyElu) {
        rx = rx > 0.f ? rx : expm1f(rx);
        ry = ry > 0.f ? ry : expm1f(ry);
    }
    *(float2*)(g_bufB + (size_t)n * (2 * D2) + 2 * t) = make_float2(rx, ry);
}

// ---------------- edge MLP via tensor cores ----------------
// Block = 128 threads (4 warps), 128 edges. Phase 1: o1 computed + packed
// big/small bf16 into smem in m16n8k16 A-fragment layout. Phase 2: 3-term
// bf16 mma vs mw2 fragments (FM2 table). Phase 3: +mb2, ReLU, dot mw3,
// width-4 reduce, store.
__global__ void __launch_bounds__(128) edge_mlp_mma_kernel(
        const int* ei, const float* ea,
        const float* mw1, const float* mb1, const float* mb2,
        const float* mw3, const float* mb3, float* out, int E) {
    __shared__ unsigned sAb[4096];
    __shared__ unsigned sAs[4096];

    int tid = threadIdx.x;
    int wid = tid >> 5;
    int lane = tid & 31;
    int blockBase = blockIdx.x * 128;
    int eW = blockBase + wid * 32;

    // prefetch this warp's 32 edges (coalesced)
    int eL = min(eW + lane, E - 1);
    int r32 = ei[eL];
    int c32 = ei[E + eL];
    float ea0v = ea[eL * 2];
    float ea1v = ea[eL * 2 + 1];

    int j0 = lane * 2;
    float w1e0 = mw1[256 * 64 + j0], w1e0b = mw1[256 * 64 + j0 + 1];
    float w1e1 = mw1[257 * 64 + j0], w1e1b = mw1[257 * 64 + j0 + 1];
    float bj0 = mb1[j0], bj1 = mb1[j0 + 1];

    // this lane's k-pair P = lane -> (t, khalf, p2)
    int tk = lane >> 3;
    int khalf = (lane >> 2) & 1;
    int p2 = lane & 3;

#pragma unroll 2
    for (int i = 0; i < 16; i++) {
        int elA = wid * 32 + 2 * i;
        int elB = elA + 1;
        int rowA = __shfl_sync(0xffffffffu, r32, 2 * i);
        int colA = __shfl_sync(0xffffffffu, c32, 2 * i);
        float eaA0 = __shfl_sync(0xffffffffu, ea0v, 2 * i);
        float eaA1 = __shfl_sync(0xffffffffu, ea1v, 2 * i);
        int rowB = __shfl_sync(0xffffffffu, r32, 2 * i + 1);
        int colB = __shfl_sync(0xffffffffu, c32, 2 * i + 1);
        float eaB0 = __shfl_sync(0xffffffffu, ea0v, 2 * i + 1);
        float eaB1 = __shfl_sync(0xffffffffu, ea1v, 2 * i + 1);

        float2 prA = *(const float2*)(g_pcomb + (size_t)rowA * 128 + j0);
        float2 pcA = *(const float2*)(g_pcomb + (size_t)colA * 128 + 64 + j0);
        float2 prB = *(const float2*)(g_pcomb + (size_t)rowB * 128 + j0);
        float2 pcB = *(const float2*)(g_pcomb + (size_t)colB * 128 + 64 + j0);

        float o1aA = fmaxf(prA.x + pcA.x + eaA0 * w1e0 + eaA1 * w1e1 + bj0, 0.f);
        float o1bA = fmaxf(prA.y + pcA.y + eaA0 * w1e0b + eaA1 * w1e1b + bj1, 0.f);
        float o1aB = fmaxf(prB.x + pcB.x + eaB0 * w1e0 + eaB1 * w1e1 + bj0, 0.f);
        float o1bB = fmaxf(prB.y + pcB.y + eaB0 * w1e0b + eaB1 * w1e1b + bj1, 0.f);

        {
            int row = elA & 15, tile = elA >> 4;
            int agg = row & 7, ahi = row >> 3;
            int slot = p2 ^ ((agg >> 1) & 3);
            int idx = (tile * 4 + tk) * 128 + (agg * 4 + slot) * 4 + khalf * 2 + ahi;
            unsigned big = pack_bf16(o1aA, o1bA);
            float lo = __uint_as_float(big << 16);
            float hi = __uint_as_float(big & 0xffff0000u);
            sAb[idx] = big;
            sAs[idx] = pack_bf16(o1aA - lo, o1bA - hi);
        }
        {
            int row = elB & 15, tile = elB >> 4;
            int agg = row & 7, ahi = row >> 3;
            int slot = p2 ^ ((agg >> 1) & 3);
            int idx = (tile * 4 + tk) * 128 + (agg * 4 + slot) * 4 + khalf * 2 + ahi;
            unsigned big = pack_bf16(o1aB, o1bB);
            float lo = __uint_as_float(big << 16);
            float hi = __uint_as_float(big & 0xffff0000u);
            sAb[idx] = big;
            sAs[idx] = pack_bf16(o1aB - lo, o1bB - hi);
        }
    }
    __syncthreads();

    // phase 2: mma — warp handles tiles 2*wid, 2*wid+1
    int g = lane >> 2;
    int tg = lane & 3;
    float d[2][4][4];
#pragma unroll
    for (int mi = 0; mi < 2; mi++)
#pragma unroll
        for (int ni = 0; ni < 4; ni++)
#pragma unroll
            for (int q = 0; q < 4; q++) d[mi][ni][q] = 0.f;

    const unsigned* Wf = (const unsigned*)g_Wf;
#pragma unroll
    for (int ts = 0; ts < 4; ts++) {
        uint4 bfr[4];
#pragma unroll
        for (int ni = 0; ni < 4; ni++)
            bfr[ni] = *(const uint4*)(Wf + FM2 + (ts * 4 + ni) * 128 + lane * 4);
#pragma unroll
        for (int mi = 0; mi < 2; mi++) {
            int tile = wid * 2 + mi;
            int base = (tile * 4 + ts) * 128 + (g * 4 + (tg ^ ((g >> 1) & 3))) * 4;
            uint4 ab = *(const uint4*)&sAb[base];
            uint4 as_ = *(const uint4*)&sAs[base];
#pragma unroll
            for (int ni = 0; ni < 4; ni++) {
                float* dd = d[mi][ni];
                mma_bf16(dd[0], dd[1], dd[2], dd[3], ab.x, ab.y, ab.z, ab.w,
                         bfr[ni].x, bfr[ni].y);
                mma_bf16(dd[0], dd[1], dd[2], dd[3], ab.x, ab.y, ab.z, ab.w,
                         bfr[ni].z, bfr[ni].w);
                mma_bf16(dd[0], dd[1], dd[2], dd[3], as_.x, as_.y, as_.z, as_.w,
                         bfr[ni].x, bfr[ni].y);
            }
        }
    }

    // phase 3: +mb2, relu, dot with mw3, reduce width-4, store
    float part[2][2] = {{0.f, 0.f}, {0.f, 0.f}};
#pragma unroll
    for (int ni = 0; ni < 4; ni++) {
        int col = ni * 8 + tg * 2;
        float b20 = mb2[col], b21 = mb2[col + 1];
        float m30 = mw3[col], m31 = mw3[col + 1];
#pragma unroll
        for (int mi = 0; mi < 2; mi++) {
            part[mi][0] += fmaxf(d[mi][ni][0] + b20, 0.f) * m30
                         + fmaxf(d[mi][ni][1] + b21, 0.f) * m31;
            part[mi][1] += fmaxf(d[mi][ni][2] + b20, 0.f) * m30
                         + fmaxf(d[mi][ni][3] + b21, 0.f) * m31;
        }
    }
#pragma unroll
    for (int o = 2; o >= 1; o >>= 1) {
#pragma unroll
        for (int mi = 0; mi < 2; mi++)
#pragma unroll
            for (int hh = 0; hh < 2; hh++)
                part[mi][hh] += __shfl_down_sync(0xffffffffu, part[mi][hh], o, 4);
    }
    if (tg == 0) {
        float b3 = mb3[0];
#pragma unroll
        for (int mi = 0; mi < 2; mi++)
#pragma unroll
            for (int hh = 0; hh < 2; hh++) {
                int e = blockBase + (wid * 2 + mi) * 16 + g + hh * 8;
                if (e < E) out[e] = part[mi][hh] + b3;
            }
    }
}

// ---------------- launch ----------------
extern "C" void kernel_launch(void* const* d_in, const int* in_sizes, int n_in,
                              void* d_out, int out_size) {
    const float* x = (const float*)d_in[0];
    const int* ei = (const int*)d_in[1];
    const float* ea = (const float*)d_in[2];
    const float* W1 = (const float*)d_in[3];
    const float* a1s = (const float*)d_in[4];
    const float* a1d = (const float*)d_in[5];
    const float* b1 = (const float*)d_in[6];
    const float* W2 = (const float*)d_in[7];
    const float* a2s = (const float*)d_in[8];
    const float* a2d = (const float*)d_in[9];
    const float* b2 = (const float*)d_in[10];
    const float* W3 = (const float*)d_in[11];
    const float* a3s = (const float*)d_in[12];
    const float* a3d = (const float*)d_in[13];
    const float* b3 = (const float*)d_in[14];
    const float* mw1 = (const float*)d_in[15];
    const float* mb1 = (const float*)d_in[16];
    const float* mw2 = (const float*)d_in[17];
    const float* mb2 = (const float*)d_in[18];
    const float* mw3 = (const float*)d_in[19];
    const float* mb3 = (const float*)d_in[20];
    float* out = (float*)d_out;

    int N = in_sizes[0] / 32;
    int E = in_sizes[1] / 2;

    int mBlocks = (N + 127) / 128;
    dim3 g256(4, mBlocks);
    dim3 g128(2, mBlocks);

    // 1) weight split into fragment tables
    wsplit_kernel<<<488, 256>>>(W1, W2, W3, mw1, mw2);
    // 2) zero degrees
    zero_deg_kernel<<<(N + 255) / 256, 256>>>(N);
    // 3) histogram
    hist_kernel<<<(E + 255) / 256, 256>>>(ei, E);
    // 4) layer-1 GEMM with fused attention dots  <-- profiled slot
    gemm_bf_kernel<0, 0, 1><<<g256, 256>>>(x, a1s, a1d, FW1, 4, N, 32);
    // 5) scan
    scan_kernel<<<1, 1024>>>(N);
    // 6) scatter
    scatter_kernel<<<(E + 255) / 256, 256>>>(ei, E);
    // layer-1 aggregation
    agg_kernel<4, 64><<<N, 128>>>(b1, 1);

    // ---- layer 2 ----
    gemm_bf_kernel<1, 0, 1><<<g256, 256>>>(x, a2s, a2d, FW2, 4, N, 256);
    agg_kernel<4, 64><<<N, 128>>>(b2, 1);

    // ---- layer 3 (atomic al accumulation; zero first) ----
    zero_al_kernel<<<(N + 255) / 256, 256>>>(N);
    gemm_bf_kernel<1, 0, 2><<<g128, 256>>>(x, a3s, a3d, FW3, 2, N, 256);
    agg_kernel<1, 128><<<N, 64>>>(b3, 0);

    // ---- edge MLP precompute (single combined GEMM) ----
    gemm_bf_kernel<1, 1, 0><<<g128, 256>>>(x, a1s, a1d, FPC, 2, N, 128);

    // ---- edge MLP via tensor cores ----
    edge_mlp_mma_kernel<<<(E + 127) / 128, 128>>>(ei, ea, mw1, mb1, mb2, mw3, mb3, out, E);
}